// round 10
// baseline (speedup 1.0000x reference)
#include <cuda_runtime.h>
#include <math.h>
#include <stdint.h>

#define KS   512
#define DD   768
#define HH   128
#define CC   16
#define EE   200
#define NALL 30000
#define NB   10
#define KC   (KS*CC)          // 8192
#define CSV_N (NALL*DD)       // 23040000
#define LDO  (CC+KS)          // 528

// ---------------- scratch (device globals; no allocation allowed) ----------
__device__ __align__(16) float g_m0[KS*DD];
__device__ __align__(16) float g_m1[KS*DD];
__device__ __align__(16) float g_m2[KS*DD];
__device__ __align__(16) float g_ctxt[KS*DD];
__device__ __align__(16) float g_gacc[KS*DD];
__device__ __align__(16) float g_hproj[KS*384];   // hl | hr | hm
__device__ __align__(16) float g_hlr[KS*256];     // hl | hr  (loop)
__device__ __align__(16) float g_he[KC*HH];
__device__ __align__(16) float g_coref[KS*KS];
__device__ __align__(16) float g_probs[KS*KS];
__device__ __align__(16) float g_p[KS];
__device__ __align__(16) float g_Wpk[DD*384];     // packed Wl|Wr|Wm
__device__ int g_rowidx[KC];

// ---------------- small helpers -------------------------------------------
__device__ __forceinline__ float warpReduceSum(float v) {
    v += __shfl_down_sync(0xffffffffu, v, 16);
    v += __shfl_down_sync(0xffffffffu, v, 8);
    v += __shfl_down_sync(0xffffffffu, v, 4);
    v += __shfl_down_sync(0xffffffffu, v, 2);
    v += __shfl_down_sync(0xffffffffu, v, 1);
    return v;
}
__device__ __forceinline__ float warpReduceMax(float v) {
    v = fmaxf(v, __shfl_down_sync(0xffffffffu, v, 16));
    v = fmaxf(v, __shfl_down_sync(0xffffffffu, v, 8));
    v = fmaxf(v, __shfl_down_sync(0xffffffffu, v, 4));
    v = fmaxf(v, __shfl_down_sync(0xffffffffu, v, 2));
    v = fmaxf(v, __shfl_down_sync(0xffffffffu, v, 1));
    return v;
}
__device__ __forceinline__ uint32_t tf32_bits(float x) {
    uint32_t u;
    asm("cvt.rna.tf32.f32 %0, %1;" : "=r"(u) : "f"(x));
    return u;
}
__device__ __forceinline__ void cp16(uint32_t dst, const void* src, uint32_t srcsize) {
    asm volatile("cp.async.cg.shared.global [%0], [%1], 16, %2;"
                 :: "r"(dst), "l"(src), "r"(srcsize));
}

// ---------------- utility kernels -----------------------------------------
// gather mention row k and zero hproj row k
__global__ void gather_m_kernel(const float* __restrict__ csv, const int* __restrict__ idx,
                                float* __restrict__ m, float* __restrict__ hproj) {
    int k = blockIdx.x;
    int t = threadIdx.x;                      // 192 threads * float4 = 768 floats
    const float4* src = (const float4*)(csv + (size_t)idx[k] * DD);
    ((float4*)(m + (size_t)k * DD))[t] = src[t];
    if (t < 96) ((float4*)(hproj + (size_t)k * 384))[t] = make_float4(0.f, 0.f, 0.f, 0.f);
}

__global__ void rowidx_kernel(const int* __restrict__ cands, const int* __restrict__ pidx,
                              int* __restrict__ rowidx) {
    int r = blockIdx.x * 256 + threadIdx.x;
    if (r < KC) {
        int k = r >> 4, c = r & 15;
        rowidx[r] = cands[pidx[k] * CC + c];
    }
}

__global__ void pack_w_kernel(const float* __restrict__ Wl, const float* __restrict__ Wr,
                              const float* __restrict__ Wm, float* __restrict__ Wpk) {
    int i = blockIdx.x * 256 + threadIdx.x;    // over DD*HH
    if (i >= DD * HH) return;
    int d = i / HH, h = i % HH;
    Wpk[(size_t)d * 384 + h]        = Wl[i];
    Wpk[(size_t)d * 384 + 128 + h]  = Wr[i];
    Wpk[(size_t)d * 384 + 256 + h]  = Wm[i];
}

// ---------------- tf32 tensor-core split-K GEMM (128x128, cp.async) --------
// C[M,N] += A*B, tf32 in / fp32 acc, mma.m16n8k8. Tiles staged with
// cp.async.cg double-buffering. A stored [m][k] (pad 20), B [k][n] (pad 132).
// Dual-A: rows from Aa for k < kSwitch else Ab (k rebased). Optional idxA
// gathers A rows. atomicAdd into pre-zeroed C. kChunk %16==0, must not
// straddle kSwitch; all kend values %8==0. Grid (N/128, M/128, splits).
__global__ __launch_bounds__(256) void gemm_tf32(
    const float* __restrict__ Aa, const float* __restrict__ Ab, int kSwitch, int lda,
    const int* __restrict__ idxA,
    const float* __restrict__ B, int ldb,
    float* __restrict__ C, int ldc, int K, int kChunk)
{
    __shared__ float As[2][128][20];    // [m][k], 16 k used + pad 4
    __shared__ float Bs[2][16][132];    // [k][n], 128 n used + pad 4

    int bn0 = blockIdx.x * 128;
    int bm0 = blockIdx.y * 128;
    int k0 = blockIdx.z * kChunk;
    int kend = min(K, k0 + kChunk);
    if (k0 >= kend) return;

    const float* Abase = (k0 >= kSwitch) ? (Ab - kSwitch) : Aa;

    int tid = threadIdx.x;
    int a_row = tid >> 1, a_kq = (tid & 1) * 8;
    const float* a_ptr;
    {
        int grow = bm0 + a_row;
        if (idxA) a_ptr = Aa + (size_t)idxA[grow] * lda;
        else      a_ptr = Abase + (size_t)grow * lda;
    }
    int b_krow = tid >> 4, b_nq = (tid & 15) * 8;

    int lane = tid & 31, warp = tid >> 5;
    int gid = lane >> 2, tg = lane & 3;
    int m0w = (warp & 3) * 32;     // 4 warps along M
    int n0w = (warp >> 2) * 64;    // 2 warps along N

    float acc[2][8][4];
    #pragma unroll
    for (int i = 0; i < 2; i++)
        #pragma unroll
        for (int j = 0; j < 8; j++)
            #pragma unroll
            for (int q = 0; q < 4; q++) acc[i][j][q] = 0.f;

    auto stage = [&](int buf, int kk) {
        #pragma unroll
        for (int s = 0; s < 8; s += 4) {
            int c0 = kk + a_kq + s;
            uint32_t ok = (c0 + 4 <= kend) ? 16u : 0u;
            const float* src = ok ? (a_ptr + c0) : a_ptr;
            uint32_t dst = (uint32_t)__cvta_generic_to_shared(&As[buf][a_row][a_kq + s]);
            cp16(dst, src, ok);
        }
        int kr = kk + b_krow;
        uint32_t okb = (kr < kend) ? 16u : 0u;
        const float* bp = okb ? (B + (size_t)kr * ldb + bn0 + b_nq) : B;
        #pragma unroll
        for (int s = 0; s < 8; s += 4) {
            uint32_t dst = (uint32_t)__cvta_generic_to_shared(&Bs[buf][b_krow][b_nq + s]);
            cp16(dst, okb ? (bp + s) : bp, okb);
        }
    };

    stage(0, k0);
    asm volatile("cp.async.commit_group;");
    asm volatile("cp.async.wait_group 0;");
    __syncthreads();

    int buf = 0;
    for (int kk = k0; kk < kend; kk += 16) {
        int nb = buf ^ 1;
        bool has_next = (kk + 16) < kend;
        if (has_next) {
            stage(nb, kk + 16);
            asm volatile("cp.async.commit_group;");
        }

        #pragma unroll
        for (int ks = 0; ks < 16; ks += 8) {
            uint32_t af[2][4];
            #pragma unroll
            for (int mt = 0; mt < 2; mt++) {
                int mrow = m0w + mt * 16 + gid;
                af[mt][0] = tf32_bits(As[buf][mrow]    [ks + tg]);
                af[mt][1] = tf32_bits(As[buf][mrow + 8][ks + tg]);
                af[mt][2] = tf32_bits(As[buf][mrow]    [ks + tg + 4]);
                af[mt][3] = tf32_bits(As[buf][mrow + 8][ks + tg + 4]);
            }
            uint32_t bf[8][2];
            #pragma unroll
            for (int nt = 0; nt < 8; nt++) {
                int ncol = n0w + nt * 8 + gid;
                bf[nt][0] = tf32_bits(Bs[buf][ks + tg]    [ncol]);
                bf[nt][1] = tf32_bits(Bs[buf][ks + tg + 4][ncol]);
            }
            #pragma unroll
            for (int mt = 0; mt < 2; mt++)
                #pragma unroll
                for (int nt = 0; nt < 8; nt++) {
                    asm volatile(
                        "mma.sync.aligned.m16n8k8.row.col.f32.tf32.tf32.f32 "
                        "{%0,%1,%2,%3}, {%4,%5,%6,%7}, {%8,%9}, {%0,%1,%2,%3};"
                        : "+f"(acc[mt][nt][0]), "+f"(acc[mt][nt][1]),
                          "+f"(acc[mt][nt][2]), "+f"(acc[mt][nt][3])
                        : "r"(af[mt][0]), "r"(af[mt][1]), "r"(af[mt][2]), "r"(af[mt][3]),
                          "r"(bf[nt][0]), "r"(bf[nt][1]));
                }
        }
        asm volatile("cp.async.wait_group 0;");
        __syncthreads();
        buf = nb;
    }

    #pragma unroll
    for (int mt = 0; mt < 2; mt++) {
        int gr = bm0 + m0w + mt * 16 + gid;
        #pragma unroll
        for (int nt = 0; nt < 8; nt++) {
            int gc = bn0 + n0w + nt * 8 + tg * 2;
            atomicAdd(&C[(size_t)gr * ldc + gc],           acc[mt][nt][0]);
            atomicAdd(&C[(size_t)gr * ldc + gc + 1],       acc[mt][nt][1]);
            atomicAdd(&C[(size_t)(gr + 8) * ldc + gc],     acc[mt][nt][2]);
            atomicAdd(&C[(size_t)(gr + 8) * ldc + gc + 1], acc[mt][nt][3]);
        }
    }
}

// ---------------- link epilogue (writes straight into out_fs cols 0..15) ---
__global__ void link_kernel(const float* __restrict__ he, const float* __restrict__ hm, int hmd,
                            const float* __restrict__ b_l, const float* __restrict__ v_l,
                            const float* __restrict__ ss, float* __restrict__ out_fs) {
    int row = blockIdx.x;     // 0..KC-1
    int k = row >> 4, c = row & 15;
    int h = threadIdx.x;      // 128
    float t = he[(size_t)row * HH + h] + hm[(size_t)k * hmd + h] + b_l[h];
    float v = fmaxf(t, 0.f) * v_l[h];
    v = warpReduceSum(v);
    __shared__ float s[4];
    int wid = h >> 5, lane = h & 31;
    if (lane == 0) s[wid] = v;
    __syncthreads();
    if (h == 0) out_fs[(size_t)k * LDO + c] = s[0] + s[1] + s[2] + s[3] + ss[k];
}

// ---------------- tiled coref scoring (param output stride) ----------------
__global__ __launch_bounds__(256) void coref_tiled(
    const float* __restrict__ hl, int hld,
    const float* __restrict__ hr, int hrd,
    const float* __restrict__ addv, const int* __restrict__ sb,
    const float* __restrict__ de, const float* __restrict__ bc,
    const float* __restrict__ vc, float* __restrict__ outc, int ldo)
{
    __shared__ float s_hl[HH][34];
    __shared__ float s_hr[HH][34];
    __shared__ float s_de[NB][132];
    __shared__ float s_vc[HH];

    int tid = threadIdx.x;
    int j0 = blockIdx.x * 32, i0 = blockIdx.y * 32;

    {
        int i = tid >> 3, hb = (tid & 7) << 4;
        const float* srcL = hl + (size_t)(i0 + i) * hld + hb;
        const float* srcR = hr + (size_t)(j0 + i) * hrd + hb;
        #pragma unroll
        for (int q = 0; q < 16; q += 4) {
            float4 v = *(const float4*)(srcL + q);
            float4 b4 = *(const float4*)(bc + hb + q);
            s_hl[hb + q + 0][i] = v.x + b4.x;
            s_hl[hb + q + 1][i] = v.y + b4.y;
            s_hl[hb + q + 2][i] = v.z + b4.z;
            s_hl[hb + q + 3][i] = v.w + b4.w;
            float4 w = *(const float4*)(srcR + q);
            s_hr[hb + q + 0][i] = w.x;
            s_hr[hb + q + 1][i] = w.y;
            s_hr[hb + q + 2][i] = w.z;
            s_hr[hb + q + 3][i] = w.w;
        }
    }
    for (int t = tid; t < NB * 32; t += 256) {
        int b = t >> 5, h4 = (t & 31) << 2;
        *(float4*)&s_de[b][h4] = *(const float4*)(de + b * HH + h4);
    }
    if (tid < 32) *(float4*)&s_vc[tid * 4] = *(const float4*)(vc + tid * 4);
    __syncthreads();

    int r = tid >> 4, c = tid & 15;
    int il = r * 2, jl = c * 2;
    int gi0 = i0 + il, gj0 = j0 + jl;

    int sbi[2] = {sb[gi0], sb[gi0 + 1]};
    int sbj[2] = {sb[gj0], sb[gj0 + 1]};
    int bkt[2][2];
    #pragma unroll
    for (int ii = 0; ii < 2; ii++)
        #pragma unroll
        for (int jj = 0; jj < 2; jj++) {
            int d = sbi[ii] - sbj[jj]; d = d < 0 ? -d : d;
            int b = 31 - __clz((unsigned)d + 1u);
            bkt[ii][jj] = b > NB - 1 ? NB - 1 : b;
        }

    float acc[2][2] = {{0.f, 0.f}, {0.f, 0.f}};
    #pragma unroll 4
    for (int h = 0; h < HH; h += 4) {
        float4 vc4 = *(const float4*)&s_vc[h];
        float al[4][2], bl[4][2];
        #pragma unroll
        for (int q = 0; q < 4; q++) {
            float2 ta = *(const float2*)&s_hl[h + q][il];
            al[q][0] = ta.x; al[q][1] = ta.y;
            float2 tb = *(const float2*)&s_hr[h + q][jl];
            bl[q][0] = tb.x; bl[q][1] = tb.y;
        }
        #pragma unroll
        for (int ii = 0; ii < 2; ii++)
            #pragma unroll
            for (int jj = 0; jj < 2; jj++) {
                float4 dv = *(const float4*)&s_de[bkt[ii][jj]][h];
                acc[ii][jj] = fmaf(fmaxf(al[0][ii] + bl[0][jj] + dv.x, 0.f), vc4.x, acc[ii][jj]);
                acc[ii][jj] = fmaf(fmaxf(al[1][ii] + bl[1][jj] + dv.y, 0.f), vc4.y, acc[ii][jj]);
                acc[ii][jj] = fmaf(fmaxf(al[2][ii] + bl[2][jj] + dv.z, 0.f), vc4.z, acc[ii][jj]);
                acc[ii][jj] = fmaf(fmaxf(al[3][ii] + bl[3][jj] + dv.w, 0.f), vc4.w, acc[ii][jj]);
            }
    }

    #pragma unroll
    for (int ii = 0; ii < 2; ii++)
        #pragma unroll
        for (int jj = 0; jj < 2; jj++) {
            int gi = gi0 + ii, gj = gj0 + jj;
            outc[(size_t)gi * ldo + gj] = (gi == gj) ? 0.f : (acc[ii][jj] + addv[gi] + addv[gj]);
        }
}

// ---------------- masked softmax + zero ctxt/gacc rows ----------------------
__global__ void softmax_kernel(const float* __restrict__ coref, const float* __restrict__ mask,
                               float* __restrict__ probs,
                               float* __restrict__ ctxt, float* __restrict__ gacc) {
    int i = blockIdx.x;
    int tid = threadIdx.x;    // 256
    if (tid < 192) {
        ((float4*)(ctxt + (size_t)i * DD))[tid] = make_float4(0.f, 0.f, 0.f, 0.f);
        ((float4*)(gacc + (size_t)i * DD))[tid] = make_float4(0.f, 0.f, 0.f, 0.f);
    }
    __shared__ float sred[8];
    __shared__ float sbc;
    int j0 = tid, j1 = tid + 256;
    bool a0 = mask[(size_t)i * KS + j0] > 0.f;
    bool a1 = mask[(size_t)i * KS + j1] > 0.f;
    float x0 = a0 ? coref[(size_t)i * KS + j0] : -1e30f;
    float x1 = a1 ? coref[(size_t)i * KS + j1] : -1e30f;
    float m = fmaxf(x0, x1);
    m = warpReduceMax(m);
    int wid = tid >> 5, lane = tid & 31;
    if (lane == 0) sred[wid] = m;
    __syncthreads();
    if (tid == 0) {
        float mm = sred[0];
        for (int w = 1; w < 8; w++) mm = fmaxf(mm, sred[w]);
        sbc = mm;
    }
    __syncthreads();
    float mx = sbc;
    float e0 = a0 ? expf(x0 - mx) : 0.f;
    float e1 = a1 ? expf(x1 - mx) : 0.f;
    float s = warpReduceSum(e0 + e1);
    __syncthreads();
    if (lane == 0) sred[wid] = s;
    __syncthreads();
    if (tid == 0) {
        float ss2 = 0.f;
        for (int w = 0; w < 8; w++) ss2 += sred[w];
        sbc = ss2;
    }
    __syncthreads();
    float inv = sbc;
    probs[(size_t)i * KS + j0] = e0 / inv;
    probs[(size_t)i * KS + j1] = e1 / inv;
}

// ---------------- fused gate blend + p projection + zero hlr ----------------
__global__ void blend_p_kernel(const float* __restrict__ m_in, const float* __restrict__ ctxt,
                               const float* __restrict__ gacc, const float* __restrict__ bg,
                               const float* __restrict__ Wp, const float* __restrict__ bp,
                               float* __restrict__ m_out, float* __restrict__ p,
                               float* __restrict__ hlr) {
    int k = blockIdx.x;
    int tid = threadIdx.x;   // 256
    if (tid < 64) ((float4*)(hlr + (size_t)k * 256))[tid] = make_float4(0.f, 0.f, 0.f, 0.f);
    float dot = 0.f;
    for (int d = tid; d < DD; d += 256) {
        size_t idx = (size_t)k * DD + d;
        float a = gacc[idx] + bg[d];
        float g = 1.f / (1.f + expf(-a));
        float v = g * m_in[idx] + (1.f - g) * ctxt[idx];
        m_out[idx] = v;
        dot = fmaf(v, Wp[d], dot);
    }
    dot = warpReduceSum(dot);
    __shared__ float s[8];
    int wid = tid >> 5, lane = tid & 31;
    if (lane == 0) s[wid] = dot;
    __syncthreads();
    if (tid == 0) {
        float t = 0.f;
        for (int w = 0; w < 8; w++) t += s[w];
        p[k] = t + bp[0];
    }
}

// ---------------- scatter rows + out_m copy ---------------------------------
__global__ void scatter_kernel(const float* __restrict__ m, const int* __restrict__ idx,
                               float* __restrict__ out, float* __restrict__ out_m) {
    int k = blockIdx.x;
    int t = threadIdx.x;   // 192
    float4 v = ((const float4*)(m + (size_t)k * DD))[t];
    ((float4*)(out_m + (size_t)k * DD))[t] = v;
    int id = idx[k];
    if (k + 1 < KS && idx[k + 1] == id) return;   // not last occurrence
    ((float4*)(out + (size_t)id * DD))[t] = v;
}

// ---------------- host side --------------------------------------------------
// Persistent streams/events: created ONCE on the first (uncaptured correctness)
// call, before the harness takes its pre-capture baseline; never destroyed.
static cudaStream_t s_sA = nullptr, s_sB = nullptr;
static cudaEvent_t s_evRoot, s_evA, s_evB, s_evProj, s_evPack;

static inline void ensure_side_streams() {
    if (!s_sA) {
        cudaStreamCreateWithFlags(&s_sA, cudaStreamNonBlocking);
        cudaStreamCreateWithFlags(&s_sB, cudaStreamNonBlocking);
        cudaEventCreateWithFlags(&s_evRoot, cudaEventDisableTiming);
        cudaEventCreateWithFlags(&s_evA, cudaEventDisableTiming);
        cudaEventCreateWithFlags(&s_evB, cudaEventDisableTiming);
        cudaEventCreateWithFlags(&s_evProj, cudaEventDisableTiming);
        cudaEventCreateWithFlags(&s_evPack, cudaEventDisableTiming);
    }
}

static inline void gemmN(cudaStream_t st, const float* A, int lda, const int* idxA,
                         const float* B, int ldb,
                         float* C, int ldc, int M, int N, int K, int splits) {
    int chunk = ((K + splits - 1) / splits + 15) & ~15;
    int zs = (K + chunk - 1) / chunk;
    dim3 grid(N / 128, M / 128, zs);
    gemm_tf32<<<grid, 256, 0, st>>>(A, A, 1 << 30, lda, idxA, B, ldb, C, ldc, K, chunk);
}

extern "C" void kernel_launch(void* const* d_in, const int* in_sizes, int n_in,
                              void* d_out, int out_size) {
    const float *csv, *ss, *mask, *ET, *Wl, *Wr, *b_c, *v_c, *de, *Wm, *We, *b_l, *v_l,
                *Wg, *bg, *Wp, *bp;
    const int *pidx, *cands, *sbeg;
    if (in_sizes[3] == 60000000) {
        csv = (const float*)d_in[0];  ss = (const float*)d_in[1];  mask = (const float*)d_in[2];
        ET  = (const float*)d_in[3];  Wl = (const float*)d_in[4];  Wr = (const float*)d_in[5];
        b_c = (const float*)d_in[6];  v_c = (const float*)d_in[7]; de = (const float*)d_in[8];
        Wm  = (const float*)d_in[9];  We = (const float*)d_in[10]; b_l = (const float*)d_in[11];
        v_l = (const float*)d_in[12]; Wg = (const float*)d_in[13]; bg = (const float*)d_in[14];
        Wp  = (const float*)d_in[15]; bp = (const float*)d_in[16];
        pidx = (const int*)d_in[17];  cands = (const int*)d_in[18]; sbeg = (const int*)d_in[19];
    } else {
        csv = (const float*)d_in[0];  ss = (const float*)d_in[1];  mask = (const float*)d_in[2];
        pidx = (const int*)d_in[3];   cands = (const int*)d_in[4]; sbeg = (const int*)d_in[5];
        ET  = (const float*)d_in[6];  Wl = (const float*)d_in[7];  Wr = (const float*)d_in[8];
        b_c = (const float*)d_in[9];  v_c = (const float*)d_in[10]; de = (const float*)d_in[11];
        Wm  = (const float*)d_in[12]; We = (const float*)d_in[13]; b_l = (const float*)d_in[14];
        v_l = (const float*)d_in[15]; Wg = (const float*)d_in[16]; bg = (const float*)d_in[17];
        Wp  = (const float*)d_in[18]; bp = (const float*)d_in[19];
    }
    float* out = (float*)d_out;
    float* out_m = out + CSV_N;
    float* out_fs = out_m + KS * DD;

    float *m0, *m1, *m2, *ctxt, *gacc, *hproj, *hlr, *he, *coref, *probs, *pvec, *Wpk;
    int* rowidx;
    cudaGetSymbolAddress((void**)&m0, g_m0);
    cudaGetSymbolAddress((void**)&m1, g_m1);
    cudaGetSymbolAddress((void**)&m2, g_m2);
    cudaGetSymbolAddress((void**)&ctxt, g_ctxt);
    cudaGetSymbolAddress((void**)&gacc, g_gacc);
    cudaGetSymbolAddress((void**)&hproj, g_hproj);
    cudaGetSymbolAddress((void**)&hlr, g_hlr);
    cudaGetSymbolAddress((void**)&he, g_he);
    cudaGetSymbolAddress((void**)&coref, g_coref);
    cudaGetSymbolAddress((void**)&probs, g_probs);
    cudaGetSymbolAddress((void**)&pvec, g_p);
    cudaGetSymbolAddress((void**)&Wpk, g_Wpk);
    cudaGetSymbolAddress((void**)&rowidx, g_rowidx);

    ensure_side_streams();
    cudaStream_t sA = s_sA, sB = s_sB;

    // fork
    cudaEventRecord(s_evRoot, 0);
    cudaStreamWaitEvent(sA, s_evRoot, 0);
    cudaStreamWaitEvent(sB, s_evRoot, 0);

    // --- branch A: the big copy as a memcpy node (copy engine, not SMs) ---
    cudaMemcpyAsync(out, csv, (size_t)CSV_N * sizeof(float),
                    cudaMemcpyDeviceToDevice, sA);
    cudaEventRecord(s_evA, sA);

    // --- branch B: weight pack + entity path ---
    pack_w_kernel<<<(DD * HH + 255) / 256, 256, 0, sB>>>(Wl, Wr, Wm, Wpk);
    cudaEventRecord(s_evPack, sB);
    rowidx_kernel<<<(KC + 255) / 256, 256, 0, sB>>>(cands, pidx, rowidx);
    cudaMemsetAsync(he, 0, (size_t)KC * HH * sizeof(float), sB);
    gemmN(sB, ET, EE, rowidx, We, HH, he, HH, KC, HH, EE, 2);

    // --- main: gather, then projections (after pack) ---
    gather_m_kernel<<<KS, 192>>>(csv, pidx, m0, hproj);
    cudaStreamWaitEvent(0, s_evPack, 0);
    gemmN(0, m0, DD, nullptr, Wpk, 384, hproj, 384, KS, 384, DD, 12);   // hl|hr|hm
    cudaEventRecord(s_evProj, 0);

    // branch B continues: link (needs hm = hproj+256)
    cudaStreamWaitEvent(sB, s_evProj, 0);
    link_kernel<<<KC, 128, 0, sB>>>(he, hproj + 256, 384, b_l, v_l, ss, out_fs);
    cudaEventRecord(s_evB, sB);

    // main: initial coref
    coref_tiled<<<dim3(KS / 32, KS / 32), 256>>>(hproj, 384, hproj + 128, 384,
                                                 ss, sbeg, de, b_c, v_c, coref, KS);

    // --- coref propagation loop (2 iterations) ---
    const float* mi = m0;
    float* mos[2] = {m1, m2};
    for (int it = 0; it < 2; it++) {
        float* mo = mos[it];
        softmax_kernel<<<KS, 256>>>(coref, mask, probs, ctxt, gacc);
        gemmN(0, probs, KS, nullptr, mi, DD, ctxt, DD, KS, DD, KS, 6);
        // fused gate GEMM: [m | ctxt] @ Wg, K=1536, chunk 256 aligned to 768
        gemm_tf32<<<dim3(DD / 128, KS / 128, 6), 256>>>(mi, ctxt, DD, DD, nullptr,
                                                        Wg, DD, gacc, DD, 2 * DD, 256);
        blend_p_kernel<<<KS, 256>>>(mi, ctxt, gacc, bg, Wp, bp, mo, pvec, hlr);
        gemmN(0, mo, DD, nullptr, Wpk, 384, hlr, 256, KS, 256, DD, 16);  // hl|hr
        if (it == 0)
            coref_tiled<<<dim3(KS / 32, KS / 32), 256>>>(hlr, 256, hlr + 128, 256,
                                                         pvec, sbeg, de, b_c, v_c, coref, KS);
        else
            coref_tiled<<<dim3(KS / 32, KS / 32), 256>>>(hlr, 256, hlr + 128, 256,
                                                         pvec, sbeg, de, b_c, v_c,
                                                         out_fs + CC, LDO);
        mi = mo;
    }

    // --- join branches, outputs ---
    cudaStreamWaitEvent(0, s_evA, 0);     // copy must be done before scatter
    scatter_kernel<<<KS, 192>>>(m2, pidx, out, out_m);
    cudaStreamWaitEvent(0, s_evB, 0);     // link branch joined before capture end
}

// round 11
// speedup vs baseline: 1.1071x; 1.1071x over previous
#include <cuda_runtime.h>
#include <math.h>
#include <stdint.h>

#define KS   512
#define DD   768
#define HH   128
#define CC   16
#define EE   200
#define NALL 30000
#define NB   10
#define KC   (KS*CC)          // 8192
#define CSV_N (NALL*DD)       // 23040000
#define LDO  (CC+KS)          // 528

// GEMM smem geometry (3-stage cp.async ring, dynamic smem)
#define AS_STRIDE 20          // floats per A row  (16 k + pad4; 80B = 16B-aligned)
#define BS_STRIDE 132         // floats per B row  (128 n + pad4; 528B = 16B-aligned)
#define AS_STAGE  (128*AS_STRIDE)   // 2560 floats
#define BS_STAGE  (16*BS_STRIDE)    // 2112 floats
#define GEMM_SMEM (3*(AS_STAGE+BS_STAGE)*4)  // 56064 bytes

// ---------------- scratch (device globals; no allocation allowed) ----------
__device__ __align__(16) float g_m0[KS*DD];
__device__ __align__(16) float g_m1[KS*DD];
__device__ __align__(16) float g_m2[KS*DD];
__device__ __align__(16) float g_ctxt[KS*DD];
__device__ __align__(16) float g_gacc[KS*DD];
__device__ __align__(16) float g_hproj[KS*384];   // hl | hr | hm
__device__ __align__(16) float g_hlr[KS*256];     // hl | hr  (loop)
__device__ __align__(16) float g_he[KC*HH];
__device__ __align__(16) float g_coref[KS*KS];
__device__ __align__(16) float g_probs[KS*KS];
__device__ __align__(16) float g_p[KS];
__device__ __align__(16) float g_Wpk[DD*384];     // packed Wl|Wr|Wm
__device__ int g_rowidx[KC];

// ---------------- small helpers -------------------------------------------
__device__ __forceinline__ float warpReduceSum(float v) {
    v += __shfl_down_sync(0xffffffffu, v, 16);
    v += __shfl_down_sync(0xffffffffu, v, 8);
    v += __shfl_down_sync(0xffffffffu, v, 4);
    v += __shfl_down_sync(0xffffffffu, v, 2);
    v += __shfl_down_sync(0xffffffffu, v, 1);
    return v;
}
__device__ __forceinline__ float warpReduceMax(float v) {
    v = fmaxf(v, __shfl_down_sync(0xffffffffu, v, 16));
    v = fmaxf(v, __shfl_down_sync(0xffffffffu, v, 8));
    v = fmaxf(v, __shfl_down_sync(0xffffffffu, v, 4));
    v = fmaxf(v, __shfl_down_sync(0xffffffffu, v, 2));
    v = fmaxf(v, __shfl_down_sync(0xffffffffu, v, 1));
    return v;
}
__device__ __forceinline__ uint32_t tf32_bits(float x) {
    uint32_t u;
    asm("cvt.rna.tf32.f32 %0, %1;" : "=r"(u) : "f"(x));
    return u;
}
__device__ __forceinline__ void cp16(uint32_t dst, const void* src, uint32_t srcsize) {
    asm volatile("cp.async.cg.shared.global [%0], [%1], 16, %2;"
                 :: "r"(dst), "l"(src), "r"(srcsize));
}

// ---------------- utility kernels -----------------------------------------
__global__ void copy4_kernel(const float4* __restrict__ in, float4* __restrict__ out, int n4) {
    for (int i = blockIdx.x * blockDim.x + threadIdx.x; i < n4; i += gridDim.x * blockDim.x)
        out[i] = in[i];
}

// gather mention row k and zero hproj row k
__global__ void gather_m_kernel(const float* __restrict__ csv, const int* __restrict__ idx,
                                float* __restrict__ m, float* __restrict__ hproj) {
    int k = blockIdx.x;
    int t = threadIdx.x;                      // 192 threads * float4 = 768 floats
    const float4* src = (const float4*)(csv + (size_t)idx[k] * DD);
    ((float4*)(m + (size_t)k * DD))[t] = src[t];
    if (t < 96) ((float4*)(hproj + (size_t)k * 384))[t] = make_float4(0.f, 0.f, 0.f, 0.f);
}

__global__ void rowidx_kernel(const int* __restrict__ cands, const int* __restrict__ pidx,
                              int* __restrict__ rowidx) {
    int r = blockIdx.x * 256 + threadIdx.x;
    if (r < KC) {
        int k = r >> 4, c = r & 15;
        rowidx[r] = cands[pidx[k] * CC + c];
    }
}

__global__ void pack_w_kernel(const float* __restrict__ Wl, const float* __restrict__ Wr,
                              const float* __restrict__ Wm, float* __restrict__ Wpk) {
    int i = blockIdx.x * 256 + threadIdx.x;    // over DD*HH
    if (i >= DD * HH) return;
    int d = i / HH, h = i % HH;
    Wpk[(size_t)d * 384 + h]        = Wl[i];
    Wpk[(size_t)d * 384 + 128 + h]  = Wr[i];
    Wpk[(size_t)d * 384 + 256 + h]  = Wm[i];
}

// ---------------- tf32 tensor-core split-K GEMM (128x128, 3-stage ring) ----
// C[M,N] += A*B, tf32 in / fp32 acc, mma.m16n8k8. Tiles staged with a
// 3-stage cp.async ring (prefetch depth 2): one commit_group per iteration
// (empty commits allowed), wait_group 1 retires the group feeding the next
// buffer. Dynamic smem (56064B). A stored [m][k] stride 20, B [k][n] stride
// 132. Dual-A: rows from Aa for k < kSwitch else Ab (k rebased). Optional
// idxA gathers A rows. atomicAdd into pre-zeroed C. kChunk %16==0, must not
// straddle kSwitch; all kend values %8==0. Grid (N/128, M/128, splits).
__global__ __launch_bounds__(256) void gemm_tf32(
    const float* __restrict__ Aa, const float* __restrict__ Ab, int kSwitch, int lda,
    const int* __restrict__ idxA,
    const float* __restrict__ B, int ldb,
    float* __restrict__ C, int ldc, int K, int kChunk)
{
    extern __shared__ float smem[];
    float* AsBase = smem;                     // 3 * AS_STAGE
    float* BsBase = smem + 3 * AS_STAGE;      // 3 * BS_STAGE

    int bn0 = blockIdx.x * 128;
    int bm0 = blockIdx.y * 128;
    int k0 = blockIdx.z * kChunk;
    int kend = min(K, k0 + kChunk);
    if (k0 >= kend) return;

    const float* Abase = (k0 >= kSwitch) ? (Ab - kSwitch) : Aa;

    int tid = threadIdx.x;
    int a_row = tid >> 1, a_kq = (tid & 1) * 8;
    const float* a_ptr;
    {
        int grow = bm0 + a_row;
        if (idxA) a_ptr = Aa + (size_t)idxA[grow] * lda;
        else      a_ptr = Abase + (size_t)grow * lda;
    }
    int b_krow = tid >> 4, b_nq = (tid & 15) * 8;

    int lane = tid & 31, warp = tid >> 5;
    int gid = lane >> 2, tg = lane & 3;
    int m0w = (warp & 3) * 32;     // 4 warps along M
    int n0w = (warp >> 2) * 64;    // 2 warps along N

    float acc[2][8][4];
    #pragma unroll
    for (int i = 0; i < 2; i++)
        #pragma unroll
        for (int j = 0; j < 8; j++)
            #pragma unroll
            for (int q = 0; q < 4; q++) acc[i][j][q] = 0.f;

    auto stage = [&](int buf, int kk) {
        float* As = AsBase + buf * AS_STAGE;
        float* Bs = BsBase + buf * BS_STAGE;
        #pragma unroll
        for (int s = 0; s < 8; s += 4) {
            int c0 = kk + a_kq + s;
            uint32_t ok = (c0 + 4 <= kend) ? 16u : 0u;
            const float* src = ok ? (a_ptr + c0) : a_ptr;
            uint32_t dst = (uint32_t)__cvta_generic_to_shared(
                As + a_row * AS_STRIDE + a_kq + s);
            cp16(dst, src, ok);
        }
        int kr = kk + b_krow;
        uint32_t okb = (kr < kend) ? 16u : 0u;
        const float* bp = okb ? (B + (size_t)kr * ldb + bn0 + b_nq) : B;
        #pragma unroll
        for (int s = 0; s < 8; s += 4) {
            uint32_t dst = (uint32_t)__cvta_generic_to_shared(
                Bs + b_krow * BS_STRIDE + b_nq + s);
            cp16(dst, okb ? (bp + s) : bp, okb);
        }
    };

    // prologue: fill stages 0 and 1 (group per stage)
    stage(0, k0);
    asm volatile("cp.async.commit_group;");
    if (k0 + 16 < kend) stage(1, k0 + 16);
    asm volatile("cp.async.commit_group;");
    asm volatile("cp.async.wait_group 1;");   // stage 0 ready
    __syncthreads();

    int buf = 0;
    for (int kk = k0; kk < kend; kk += 16) {
        // prefetch kk+32 into buffer (buf+2)%3 (last computed 2 iters ago)
        int pb = buf + 2; if (pb >= 3) pb -= 3;
        if (kk + 32 < kend) stage(pb, kk + 32);
        asm volatile("cp.async.commit_group;");

        const float* As = AsBase + buf * AS_STAGE;
        const float* Bs = BsBase + buf * BS_STAGE;
        #pragma unroll
        for (int ks = 0; ks < 16; ks += 8) {
            uint32_t af[2][4];
            #pragma unroll
            for (int mt = 0; mt < 2; mt++) {
                int mrow = m0w + mt * 16 + gid;
                af[mt][0] = tf32_bits(As[mrow * AS_STRIDE + ks + tg]);
                af[mt][1] = tf32_bits(As[(mrow + 8) * AS_STRIDE + ks + tg]);
                af[mt][2] = tf32_bits(As[mrow * AS_STRIDE + ks + tg + 4]);
                af[mt][3] = tf32_bits(As[(mrow + 8) * AS_STRIDE + ks + tg + 4]);
            }
            uint32_t bf[8][2];
            #pragma unroll
            for (int nt = 0; nt < 8; nt++) {
                int ncol = n0w + nt * 8 + gid;
                bf[nt][0] = tf32_bits(Bs[(ks + tg) * BS_STRIDE + ncol]);
                bf[nt][1] = tf32_bits(Bs[(ks + tg + 4) * BS_STRIDE + ncol]);
            }
            #pragma unroll
            for (int mt = 0; mt < 2; mt++)
                #pragma unroll
                for (int nt = 0; nt < 8; nt++) {
                    asm volatile(
                        "mma.sync.aligned.m16n8k8.row.col.f32.tf32.tf32.f32 "
                        "{%0,%1,%2,%3}, {%4,%5,%6,%7}, {%8,%9}, {%0,%1,%2,%3};"
                        : "+f"(acc[mt][nt][0]), "+f"(acc[mt][nt][1]),
                          "+f"(acc[mt][nt][2]), "+f"(acc[mt][nt][3])
                        : "r"(af[mt][0]), "r"(af[mt][1]), "r"(af[mt][2]), "r"(af[mt][3]),
                          "r"(bf[nt][0]), "r"(bf[nt][1]));
                }
        }
        // retire the group feeding the NEXT buffer (most recent stays in flight)
        asm volatile("cp.async.wait_group 1;");
        __syncthreads();
        buf = buf + 1; if (buf >= 3) buf -= 3;
    }

    #pragma unroll
    for (int mt = 0; mt < 2; mt++) {
        int gr = bm0 + m0w + mt * 16 + gid;
        #pragma unroll
        for (int nt = 0; nt < 8; nt++) {
            int gc = bn0 + n0w + nt * 8 + tg * 2;
            atomicAdd(&C[(size_t)gr * ldc + gc],           acc[mt][nt][0]);
            atomicAdd(&C[(size_t)gr * ldc + gc + 1],       acc[mt][nt][1]);
            atomicAdd(&C[(size_t)(gr + 8) * ldc + gc],     acc[mt][nt][2]);
            atomicAdd(&C[(size_t)(gr + 8) * ldc + gc + 1], acc[mt][nt][3]);
        }
    }
}

// ---------------- link epilogue (writes straight into out_fs cols 0..15) ---
__global__ void link_kernel(const float* __restrict__ he, const float* __restrict__ hm, int hmd,
                            const float* __restrict__ b_l, const float* __restrict__ v_l,
                            const float* __restrict__ ss, float* __restrict__ out_fs) {
    int row = blockIdx.x;     // 0..KC-1
    int k = row >> 4, c = row & 15;
    int h = threadIdx.x;      // 128
    float t = he[(size_t)row * HH + h] + hm[(size_t)k * hmd + h] + b_l[h];
    float v = fmaxf(t, 0.f) * v_l[h];
    v = warpReduceSum(v);
    __shared__ float s[4];
    int wid = h >> 5, lane = h & 31;
    if (lane == 0) s[wid] = v;
    __syncthreads();
    if (h == 0) out_fs[(size_t)k * LDO + c] = s[0] + s[1] + s[2] + s[3] + ss[k];
}

// ---------------- tiled coref scoring (param output stride) ----------------
__global__ __launch_bounds__(256) void coref_tiled(
    const float* __restrict__ hl, int hld,
    const float* __restrict__ hr, int hrd,
    const float* __restrict__ addv, const int* __restrict__ sb,
    const float* __restrict__ de, const float* __restrict__ bc,
    const float* __restrict__ vc, float* __restrict__ outc, int ldo)
{
    __shared__ float s_hl[HH][34];
    __shared__ float s_hr[HH][34];
    __shared__ float s_de[NB][132];
    __shared__ float s_vc[HH];

    int tid = threadIdx.x;
    int j0 = blockIdx.x * 32, i0 = blockIdx.y * 32;

    {
        int i = tid >> 3, hb = (tid & 7) << 4;
        const float* srcL = hl + (size_t)(i0 + i) * hld + hb;
        const float* srcR = hr + (size_t)(j0 + i) * hrd + hb;
        #pragma unroll
        for (int q = 0; q < 16; q += 4) {
            float4 v = *(const float4*)(srcL + q);
            float4 b4 = *(const float4*)(bc + hb + q);
            s_hl[hb + q + 0][i] = v.x + b4.x;
            s_hl[hb + q + 1][i] = v.y + b4.y;
            s_hl[hb + q + 2][i] = v.z + b4.z;
            s_hl[hb + q + 3][i] = v.w + b4.w;
            float4 w = *(const float4*)(srcR + q);
            s_hr[hb + q + 0][i] = w.x;
            s_hr[hb + q + 1][i] = w.y;
            s_hr[hb + q + 2][i] = w.z;
            s_hr[hb + q + 3][i] = w.w;
        }
    }
    for (int t = tid; t < NB * 32; t += 256) {
        int b = t >> 5, h4 = (t & 31) << 2;
        *(float4*)&s_de[b][h4] = *(const float4*)(de + b * HH + h4);
    }
    if (tid < 32) *(float4*)&s_vc[tid * 4] = *(const float4*)(vc + tid * 4);
    __syncthreads();

    int r = tid >> 4, c = tid & 15;
    int il = r * 2, jl = c * 2;
    int gi0 = i0 + il, gj0 = j0 + jl;

    int sbi[2] = {sb[gi0], sb[gi0 + 1]};
    int sbj[2] = {sb[gj0], sb[gj0 + 1]};
    int bkt[2][2];
    #pragma unroll
    for (int ii = 0; ii < 2; ii++)
        #pragma unroll
        for (int jj = 0; jj < 2; jj++) {
            int d = sbi[ii] - sbj[jj]; d = d < 0 ? -d : d;
            int b = 31 - __clz((unsigned)d + 1u);
            bkt[ii][jj] = b > NB - 1 ? NB - 1 : b;
        }

    float acc[2][2] = {{0.f, 0.f}, {0.f, 0.f}};
    #pragma unroll 4
    for (int h = 0; h < HH; h += 4) {
        float4 vc4 = *(const float4*)&s_vc[h];
        float al[4][2], bl[4][2];
        #pragma unroll
        for (int q = 0; q < 4; q++) {
            float2 ta = *(const float2*)&s_hl[h + q][il];
            al[q][0] = ta.x; al[q][1] = ta.y;
            float2 tb = *(const float2*)&s_hr[h + q][jl];
            bl[q][0] = tb.x; bl[q][1] = tb.y;
        }
        #pragma unroll
        for (int ii = 0; ii < 2; ii++)
            #pragma unroll
            for (int jj = 0; jj < 2; jj++) {
                float4 dv = *(const float4*)&s_de[bkt[ii][jj]][h];
                acc[ii][jj] = fmaf(fmaxf(al[0][ii] + bl[0][jj] + dv.x, 0.f), vc4.x, acc[ii][jj]);
                acc[ii][jj] = fmaf(fmaxf(al[1][ii] + bl[1][jj] + dv.y, 0.f), vc4.y, acc[ii][jj]);
                acc[ii][jj] = fmaf(fmaxf(al[2][ii] + bl[2][jj] + dv.z, 0.f), vc4.z, acc[ii][jj]);
                acc[ii][jj] = fmaf(fmaxf(al[3][ii] + bl[3][jj] + dv.w, 0.f), vc4.w, acc[ii][jj]);
            }
    }

    #pragma unroll
    for (int ii = 0; ii < 2; ii++)
        #pragma unroll
        for (int jj = 0; jj < 2; jj++) {
            int gi = gi0 + ii, gj = gj0 + jj;
            outc[(size_t)gi * ldo + gj] = (gi == gj) ? 0.f : (acc[ii][jj] + addv[gi] + addv[gj]);
        }
}

// ---------------- masked softmax + zero ctxt/gacc rows ----------------------
__global__ void softmax_kernel(const float* __restrict__ coref, const float* __restrict__ mask,
                               float* __restrict__ probs,
                               float* __restrict__ ctxt, float* __restrict__ gacc) {
    int i = blockIdx.x;
    int tid = threadIdx.x;    // 256
    if (tid < 192) {
        ((float4*)(ctxt + (size_t)i * DD))[tid] = make_float4(0.f, 0.f, 0.f, 0.f);
        ((float4*)(gacc + (size_t)i * DD))[tid] = make_float4(0.f, 0.f, 0.f, 0.f);
    }
    __shared__ float sred[8];
    __shared__ float sbc;
    int j0 = tid, j1 = tid + 256;
    bool a0 = mask[(size_t)i * KS + j0] > 0.f;
    bool a1 = mask[(size_t)i * KS + j1] > 0.f;
    float x0 = a0 ? coref[(size_t)i * KS + j0] : -1e30f;
    float x1 = a1 ? coref[(size_t)i * KS + j1] : -1e30f;
    float m = fmaxf(x0, x1);
    m = warpReduceMax(m);
    int wid = tid >> 5, lane = tid & 31;
    if (lane == 0) sred[wid] = m;
    __syncthreads();
    if (tid == 0) {
        float mm = sred[0];
        for (int w = 1; w < 8; w++) mm = fmaxf(mm, sred[w]);
        sbc = mm;
    }
    __syncthreads();
    float mx = sbc;
    float e0 = a0 ? expf(x0 - mx) : 0.f;
    float e1 = a1 ? expf(x1 - mx) : 0.f;
    float s = warpReduceSum(e0 + e1);
    __syncthreads();
    if (lane == 0) sred[wid] = s;
    __syncthreads();
    if (tid == 0) {
        float ss2 = 0.f;
        for (int w = 0; w < 8; w++) ss2 += sred[w];
        sbc = ss2;
    }
    __syncthreads();
    float inv = sbc;
    probs[(size_t)i * KS + j0] = e0 / inv;
    probs[(size_t)i * KS + j1] = e1 / inv;
}

// ---------------- fused gate blend + p projection + zero hlr ----------------
__global__ void blend_p_kernel(const float* __restrict__ m_in, const float* __restrict__ ctxt,
                               const float* __restrict__ gacc, const float* __restrict__ bg,
                               const float* __restrict__ Wp, const float* __restrict__ bp,
                               float* __restrict__ m_out, float* __restrict__ p,
                               float* __restrict__ hlr) {
    int k = blockIdx.x;
    int tid = threadIdx.x;   // 256
    if (tid < 64) ((float4*)(hlr + (size_t)k * 256))[tid] = make_float4(0.f, 0.f, 0.f, 0.f);
    float dot = 0.f;
    for (int d = tid; d < DD; d += 256) {
        size_t idx = (size_t)k * DD + d;
        float a = gacc[idx] + bg[d];
        float g = 1.f / (1.f + expf(-a));
        float v = g * m_in[idx] + (1.f - g) * ctxt[idx];
        m_out[idx] = v;
        dot = fmaf(v, Wp[d], dot);
    }
    dot = warpReduceSum(dot);
    __shared__ float s[8];
    int wid = tid >> 5, lane = tid & 31;
    if (lane == 0) s[wid] = dot;
    __syncthreads();
    if (tid == 0) {
        float t = 0.f;
        for (int w = 0; w < 8; w++) t += s[w];
        p[k] = t + bp[0];
    }
}

// ---------------- scatter rows + out_m copy ---------------------------------
__global__ void scatter_kernel(const float* __restrict__ m, const int* __restrict__ idx,
                               float* __restrict__ out, float* __restrict__ out_m) {
    int k = blockIdx.x;
    int t = threadIdx.x;   // 192
    float4 v = ((const float4*)(m + (size_t)k * DD))[t];
    ((float4*)(out_m + (size_t)k * DD))[t] = v;
    int id = idx[k];
    if (k + 1 < KS && idx[k + 1] == id) return;   // not last occurrence
    ((float4*)(out + (size_t)id * DD))[t] = v;
}

// ---------------- host side --------------------------------------------------
// Persistent streams/events: created ONCE on the first (uncaptured correctness)
// call, before the harness takes its pre-capture baseline; never destroyed.
static cudaStream_t s_sA = nullptr, s_sB = nullptr;
static cudaEvent_t s_evRoot, s_evA, s_evB, s_evProj;

static inline void ensure_side_streams() {
    if (!s_sA) {
        cudaStreamCreateWithFlags(&s_sA, cudaStreamNonBlocking);
        cudaStreamCreateWithFlags(&s_sB, cudaStreamNonBlocking);
        cudaEventCreateWithFlags(&s_evRoot, cudaEventDisableTiming);
        cudaEventCreateWithFlags(&s_evA, cudaEventDisableTiming);
        cudaEventCreateWithFlags(&s_evB, cudaEventDisableTiming);
        cudaEventCreateWithFlags(&s_evProj, cudaEventDisableTiming);
        cudaFuncSetAttribute(gemm_tf32, cudaFuncAttributeMaxDynamicSharedMemorySize,
                             GEMM_SMEM);
    }
}

static inline void gemmN(cudaStream_t st, const float* A, int lda, const int* idxA,
                         const float* B, int ldb,
                         float* C, int ldc, int M, int N, int K, int splits) {
    int chunk = ((K + splits - 1) / splits + 15) & ~15;
    int zs = (K + chunk - 1) / chunk;
    dim3 grid(N / 128, M / 128, zs);
    gemm_tf32<<<grid, 256, GEMM_SMEM, st>>>(A, A, 1 << 30, lda, idxA, B, ldb, C, ldc, K, chunk);
}

extern "C" void kernel_launch(void* const* d_in, const int* in_sizes, int n_in,
                              void* d_out, int out_size) {
    const float *csv, *ss, *mask, *ET, *Wl, *Wr, *b_c, *v_c, *de, *Wm, *We, *b_l, *v_l,
                *Wg, *bg, *Wp, *bp;
    const int *pidx, *cands, *sbeg;
    if (in_sizes[3] == 60000000) {
        csv = (const float*)d_in[0];  ss = (const float*)d_in[1];  mask = (const float*)d_in[2];
        ET  = (const float*)d_in[3];  Wl = (const float*)d_in[4];  Wr = (const float*)d_in[5];
        b_c = (const float*)d_in[6];  v_c = (const float*)d_in[7]; de = (const float*)d_in[8];
        Wm  = (const float*)d_in[9];  We = (const float*)d_in[10]; b_l = (const float*)d_in[11];
        v_l = (const float*)d_in[12]; Wg = (const float*)d_in[13]; bg = (const float*)d_in[14];
        Wp  = (const float*)d_in[15]; bp = (const float*)d_in[16];
        pidx = (const int*)d_in[17];  cands = (const int*)d_in[18]; sbeg = (const int*)d_in[19];
    } else {
        csv = (const float*)d_in[0];  ss = (const float*)d_in[1];  mask = (const float*)d_in[2];
        pidx = (const int*)d_in[3];   cands = (const int*)d_in[4]; sbeg = (const int*)d_in[5];
        ET  = (const float*)d_in[6];  Wl = (const float*)d_in[7];  Wr = (const float*)d_in[8];
        b_c = (const float*)d_in[9];  v_c = (const float*)d_in[10]; de = (const float*)d_in[11];
        Wm  = (const float*)d_in[12]; We = (const float*)d_in[13]; b_l = (const float*)d_in[14];
        v_l = (const float*)d_in[15]; Wg = (const float*)d_in[16]; bg = (const float*)d_in[17];
        Wp  = (const float*)d_in[18]; bp = (const float*)d_in[19];
    }
    float* out = (float*)d_out;
    float* out_m = out + CSV_N;
    float* out_fs = out_m + KS * DD;

    float *m0, *m1, *m2, *ctxt, *gacc, *hproj, *hlr, *he, *coref, *probs, *pvec, *Wpk;
    int* rowidx;
    cudaGetSymbolAddress((void**)&m0, g_m0);
    cudaGetSymbolAddress((void**)&m1, g_m1);
    cudaGetSymbolAddress((void**)&m2, g_m2);
    cudaGetSymbolAddress((void**)&ctxt, g_ctxt);
    cudaGetSymbolAddress((void**)&gacc, g_gacc);
    cudaGetSymbolAddress((void**)&hproj, g_hproj);
    cudaGetSymbolAddress((void**)&hlr, g_hlr);
    cudaGetSymbolAddress((void**)&he, g_he);
    cudaGetSymbolAddress((void**)&coref, g_coref);
    cudaGetSymbolAddress((void**)&probs, g_probs);
    cudaGetSymbolAddress((void**)&pvec, g_p);
    cudaGetSymbolAddress((void**)&Wpk, g_Wpk);
    cudaGetSymbolAddress((void**)&rowidx, g_rowidx);

    ensure_side_streams();
    cudaStream_t sA = s_sA, sB = s_sB;

    // fork
    cudaEventRecord(s_evRoot, 0);
    cudaStreamWaitEvent(sA, s_evRoot, 0);
    cudaStreamWaitEvent(sB, s_evRoot, 0);

    // --- branch A: the big copy (independent until scatter) ---
    copy4_kernel<<<2048, 256, 0, sA>>>((const float4*)csv, (float4*)out, CSV_N / 4);
    cudaEventRecord(s_evA, sA);

    // --- branch B: entity path ---
    rowidx_kernel<<<(KC + 255) / 256, 256, 0, sB>>>(cands, pidx, rowidx);
    cudaMemsetAsync(he, 0, (size_t)KC * HH * sizeof(float), sB);
    gemmN(sB, ET, EE, rowidx, We, HH, he, HH, KC, HH, EE, 2);

    // --- main: gather + projections ---
    gather_m_kernel<<<KS, 192>>>(csv, pidx, m0, hproj);
    pack_w_kernel<<<(DD * HH + 255) / 256, 256>>>(Wl, Wr, Wm, Wpk);
    gemmN(0, m0, DD, nullptr, Wpk, 384, hproj, 384, KS, 384, DD, 12);   // hl|hr|hm
    cudaEventRecord(s_evProj, 0);

    // branch B continues: link (needs hm = hproj+256)
    cudaStreamWaitEvent(sB, s_evProj, 0);
    link_kernel<<<KC, 128, 0, sB>>>(he, hproj + 256, 384, b_l, v_l, ss, out_fs);
    cudaEventRecord(s_evB, sB);

    // main: initial coref
    coref_tiled<<<dim3(KS / 32, KS / 32), 256>>>(hproj, 384, hproj + 128, 384,
                                                 ss, sbeg, de, b_c, v_c, coref, KS);

    // --- coref propagation loop (2 iterations) ---
    const float* mi = m0;
    float* mos[2] = {m1, m2};
    for (int it = 0; it < 2; it++) {
        float* mo = mos[it];
        softmax_kernel<<<KS, 256>>>(coref, mask, probs, ctxt, gacc);
        gemmN(0, probs, KS, nullptr, mi, DD, ctxt, DD, KS, DD, KS, 6);
        // fused gate GEMM: [m | ctxt] @ Wg, K=1536, chunk 256 aligned to 768
        gemm_tf32<<<dim3(DD / 128, KS / 128, 6), 256, GEMM_SMEM>>>(
            mi, ctxt, DD, DD, nullptr, Wg, DD, gacc, DD, 2 * DD, 256);
        blend_p_kernel<<<KS, 256>>>(mi, ctxt, gacc, bg, Wp, bp, mo, pvec, hlr);
        gemmN(0, mo, DD, nullptr, Wpk, 384, hlr, 256, KS, 256, DD, 16);  // hl|hr
        if (it == 0)
            coref_tiled<<<dim3(KS / 32, KS / 32), 256>>>(hlr, 256, hlr + 128, 256,
                                                         pvec, sbeg, de, b_c, v_c, coref, KS);
        else
            coref_tiled<<<dim3(KS / 32, KS / 32), 256>>>(hlr, 256, hlr + 128, 256,
                                                         pvec, sbeg, de, b_c, v_c,
                                                         out_fs + CC, LDO);
        mi = mo;
    }

    // --- join branches, outputs ---
    cudaStreamWaitEvent(0, s_evA, 0);     // copy must be done before scatter
    scatter_kernel<<<KS, 192>>>(m2, pidx, out, out_m);
    cudaStreamWaitEvent(0, s_evB, 0);     // link branch joined before capture end
}